// round 16
// baseline (speedup 1.0000x reference)
#include <cuda_runtime.h>
#include <cuda_fp16.h>
#include <cstdint>
#include <math.h>

#define TOKENS   2048
#define DMODEL   1024
#define HIDDEN   2048
#define NEXP     8
#define VOCABSZ  32000
#define LN_EPS   1e-5f

#define MT 128
#define NT 256
#define KCH 32
#define NSTG 4
#define ABLK_B   10240
#define BBLK_B   16896
#define ABLK_H   5120
#define BBLK_H   8448
#define STG2 (2 * (ABLK_B + BBLK_B))
#define MBOFF (NSTG * STG2)
#define SMEM_SZ (MBOFF + 128)

#define NSLOTPAD 5120
#define SLOTTILES 40
#define NSM 152

// ---------------- scratch ----------------------------------------------------
__device__ float g_w  [TOKENS * 2];
__device__ int   g_eidx[TOKENS * 2];
__device__ int   g_slot[TOKENS * 2];
__device__ int   g_tokOfSlot[NSLOTPAD];
__device__ int   g_cnt[NEXP];
__device__ int   g_off[NEXP + 1];
__device__ int   g_mOff[NEXP];
__device__ int   g_mtot;
__device__ float g_y  [NSLOTPAD * DMODEL];
__device__ __align__(16) __half g_hpk [SLOTTILES * 32 * ABLK_H];
__device__ __align__(16) __half g_apk [SLOTTILES * 64 * ABLK_H];
__device__ __align__(16) __half g_xpk [16 * 32 * ABLK_H];
__device__ __align__(16) __half g_Whp [125 * 32 * BBLK_H];
__device__ __align__(16) __half g_W1p [NEXP * 8 * 32 * BBLK_H];
__device__ __align__(16) __half g_W2p [NEXP * 4 * 64 * BBLK_H];

// ---------------- helpers ----------------------------------------------------
__device__ __forceinline__ uint32_t h2u(__half2 h) {
    return *reinterpret_cast<uint32_t*>(&h);
}
__device__ __forceinline__ uint32_t smem_u32(const void* p) {
    uint32_t a;
    asm("{ .reg .u64 t; cvta.to.shared.u64 t, %1; cvt.u32.u64 %0, t; }"
        : "=r"(a) : "l"(p));
    return a;
}
__device__ __forceinline__ void mma_f16(float c[4], const uint32_t a[4],
                                        const uint32_t b[2]) {
    asm volatile(
        "mma.sync.aligned.m16n8k16.row.col.f32.f16.f16.f32 "
        "{%0,%1,%2,%3}, {%4,%5,%6,%7}, {%8,%9}, {%0,%1,%2,%3};"
        : "+f"(c[0]), "+f"(c[1]), "+f"(c[2]), "+f"(c[3])
        : "r"(a[0]), "r"(a[1]), "r"(a[2]), "r"(a[3]), "r"(b[0]), "r"(b[1]));
}
__device__ __forceinline__ void ldsm4(uint32_t r[4], uint32_t addr) {
    asm volatile("ldmatrix.sync.aligned.m8n8.x4.shared.b16 {%0,%1,%2,%3}, [%4];"
                 : "=r"(r[0]), "=r"(r[1]), "=r"(r[2]), "=r"(r[3]) : "r"(addr));
}
__device__ __forceinline__ void ldsm4t(uint32_t r[4], uint32_t addr) {
    asm volatile("ldmatrix.sync.aligned.m8n8.x4.trans.shared.b16 {%0,%1,%2,%3}, [%4];"
                 : "=r"(r[0]), "=r"(r[1]), "=r"(r[2]), "=r"(r[3]) : "r"(addr));
}
#define MBAR_INIT(a, n) \
    asm volatile("mbarrier.init.shared.b64 [%0], %1;" :: "r"((uint32_t)(a)), "r"((uint32_t)(n)) : "memory")
#define MBAR_EXPECT_TX(a, b) \
    asm volatile("mbarrier.arrive.expect_tx.shared.b64 _, [%0], %1;" :: "r"((uint32_t)(a)), "r"((uint32_t)(b)) : "memory")
#define MBAR_ARRIVE(a) \
    asm volatile("mbarrier.arrive.shared.b64 _, [%0];" :: "r"((uint32_t)(a)) : "memory")
#define MBAR_WAIT(a, par) do { \
    uint32_t _mb = (uint32_t)(a); uint32_t _pa = (uint32_t)(par); uint32_t _dn; \
    asm volatile("{\n\t.reg .pred p;\n\t" \
        "mbarrier.try_wait.parity.acquire.cta.shared::cta.b64 p, [%1], %2;\n\t" \
        "selp.b32 %0, 1, 0, p;\n\t}" : "=r"(_dn) : "r"(_mb), "r"(_pa) : "memory"); \
    if (!_dn) { \
        asm volatile("{\n\t.reg .pred P1;\n\t" \
            "WL_%=:\n\t" \
            "mbarrier.try_wait.parity.acquire.cta.shared::cta.b64 P1, [%0], %1, 0x989680;\n\t" \
            "@P1 bra.uni WD_%=;\n\t" \
            "bra.uni WL_%=;\n\t" \
            "WD_%=:\n\t}" :: "r"(_mb), "r"(_pa) : "memory"); \
    } } while (0)
__device__ __forceinline__ void bulk_ld(uint32_t dst, const void* src,
                                        uint32_t bytes, uint32_t mbar) {
    asm volatile(
        "cp.async.bulk.shared::cluster.global.mbarrier::complete_tx::bytes "
        "[%0], [%1], %2, [%3];"
        :: "r"(dst), "l"(src), "r"(bytes), "r"(mbar) : "memory");
}

// ---------------- pack unit helper -------------------------------------------
__device__ __forceinline__ void pack_unit(const float* src, __half* dst) {
    float4 v0 = *(const float4*)src;
    float4 v1 = *(const float4*)(src + 4);
    uint4 o;
    o.x = h2u(__floats2half2_rn(v0.x, v0.y));
    o.y = h2u(__floats2half2_rn(v0.z, v0.w));
    o.z = h2u(__floats2half2_rn(v1.x, v1.y));
    o.w = h2u(__floats2half2_rn(v1.z, v1.w));
    *(uint4*)dst = o;
}

#define WH_UNITS (125 * 32 * 32 * 32)
#define W1_UNITS (NEXP * 8 * 32 * 32 * 32)
#define W2_UNITS (NEXP * 4 * 64 * 32 * 32)
#define W1BLOCKS ((W1_UNITS + 255) / 256)
#define P2BLOCKS ((W2_UNITS + WH_UNITS + 255) / 256)

// ---------------- stream0: pack W1 + gate ------------------------------------
__global__ void prep1_kernel(const int* __restrict__ x,
                             const float* __restrict__ embed,
                             const float* __restrict__ Wg,
                             const float* __restrict__ bg,
                             const float* __restrict__ W1) {
    if (blockIdx.x < W1BLOCKS) {
        int i = blockIdx.x * blockDim.x + threadIdx.x;
        if (i >= W1_UNITS) return;
        int u = i & 31, k = (i >> 5) & 31, ch = (i >> 10) & 31, st = (i >> 15) & 7, e = i >> 18;
        pack_unit(W1 + (size_t)e * DMODEL * HIDDEN + (size_t)(ch * 32 + k) * HIDDEN + st * 256 + u * 8,
                  g_W1p + (size_t)((e * 8 + st) * 32 + ch) * BBLK_H + k * 264 + u * 8);
        return;
    }
    int t   = blockIdx.x - W1BLOCKS;
    int tid = threadIdx.x;
    int row = x[t];
    float4 v = ((const float4*)(embed + (size_t)row * DMODEL))[tid];

    float p[NEXP];
#pragma unroll
    for (int e = 0; e < NEXP; e++) p[e] = 0.f;
    float hv[4] = {v.x, v.y, v.z, v.w};
    int d0 = tid * 4;
#pragma unroll
    for (int j = 0; j < 4; j++) {
        const float* wgr = Wg + (size_t)(d0 + j) * NEXP;
#pragma unroll
        for (int e = 0; e < NEXP; e++) p[e] += hv[j] * wgr[e];
    }
#pragma unroll
    for (int e = 0; e < NEXP; e++)
        for (int o = 16; o > 0; o >>= 1)
            p[e] += __shfl_xor_sync(0xffffffffu, p[e], o);

    __shared__ float red[8][NEXP];
    int warp = tid >> 5, lane = tid & 31;
    if (lane == 0)
#pragma unroll
        for (int e = 0; e < NEXP; e++) red[warp][e] = p[e];
    __syncthreads();

    if (tid == 0) {
        float g[NEXP];
#pragma unroll
        for (int e = 0; e < NEXP; e++) {
            g[e] = bg[e];
#pragma unroll
            for (int w = 0; w < 8; w++) g[e] += red[w][e];
        }
        float mx = g[0];
#pragma unroll
        for (int e = 1; e < NEXP; e++) mx = fmaxf(mx, g[e]);
        float s = 0.f, pr[NEXP];
#pragma unroll
        for (int e = 0; e < NEXP; e++) { pr[e] = expf(g[e] - mx); s += pr[e]; }
        float inv = 1.f / s;
#pragma unroll
        for (int e = 0; e < NEXP; e++) pr[e] *= inv;

        int i0 = 0;
#pragma unroll
        for (int e = 1; e < NEXP; e++) if (pr[e] > pr[i0]) i0 = e;
        int i1 = (i0 == 0) ? 1 : 0;
#pragma unroll
        for (int e = 0; e < NEXP; e++)
            if (e != i0 && pr[e] > pr[i1]) i1 = e;

        g_w[2 * t]     = pr[i0];  g_eidx[2 * t]     = i0;
        g_w[2 * t + 1] = pr[i1];  g_eidx[2 * t + 1] = i1;
    }
}

// ---------------- stream1: pack W2 + Wh --------------------------------------
__global__ void prep2_kernel(const float* __restrict__ W2,
                             const float* __restrict__ Wh) {
    int idx = blockIdx.x * blockDim.x + threadIdx.x;
    if (idx < W2_UNITS) {
        int u = idx & 31, k = (idx >> 5) & 31, ch = (idx >> 10) & 63, st = (idx >> 16) & 3, e = idx >> 18;
        pack_unit(W2 + (size_t)e * HIDDEN * DMODEL + (size_t)(ch * 32 + k) * DMODEL + st * 256 + u * 8,
                  g_W2p + (size_t)((e * 4 + st) * 64 + ch) * BBLK_H + k * 264 + u * 8);
    } else if (idx < W2_UNITS + WH_UNITS) {
        int i = idx - W2_UNITS;
        int u = i & 31, k = (i >> 5) & 31, ch = (i >> 10) & 31, st = i >> 15;
        pack_unit(Wh + (size_t)(ch * 32 + k) * VOCABSZ + st * 256 + u * 8,
                  g_Whp + (size_t)(st * 32 + ch) * BBLK_H + k * 264 + u * 8);
    }
}

// ---------------- count + scan + slot assignment -----------------------------
__global__ void scan_assign_kernel() {
    __shared__ int s_cnt[NEXP];
    __shared__ int s_off[NEXP + 1];
    __shared__ int s_cur[NEXP];
    int tid = threadIdx.x;
    for (int i = tid; i < NSLOTPAD; i += blockDim.x) g_tokOfSlot[i] = 0;
    if (tid < NEXP) { s_cnt[tid] = 0; s_cur[tid] = 0; }
    __syncthreads();
    for (int i = tid; i < TOKENS * 2; i += blockDim.x)
        atomicAdd(&s_cnt[g_eidx[i]], 1);
    __syncthreads();
    if (tid == 0) {
        s_off[0] = 0;
        for (int e = 0; e < NEXP; e++) {
            s_off[e + 1] = s_off[e] + ((s_cnt[e] + 127) & ~127);
            g_cnt[e] = s_cnt[e];
        }
        for (int e = 0; e <= NEXP; e++) g_off[e] = s_off[e];
        for (int e = 0; e < NEXP; e++) g_mOff[e] = s_off[e] >> 7;
        g_mtot = s_off[NEXP] >> 7;
    }
    __syncthreads();
    for (int t = tid; t < TOKENS; t += blockDim.x) {
#pragma unroll
        for (int k = 0; k < 2; k++) {
            int e = g_eidx[2 * t + k];
            int pos = atomicAdd(&s_cur[e], 1);
            int slot = s_off[e] + pos;
            g_slot[2 * t + k] = slot;
            g_tokOfSlot[slot] = t;
        }
    }
}

// ---------------- pack FFN1 A ------------------------------------------------
__global__ void pack_h_kernel(const int* __restrict__ x,
                              const float* __restrict__ embed) {
    int idx = blockIdx.x * blockDim.x + threadIdx.x;
    if (idx >= NSLOTPAD * 128) return;
    int slot = idx >> 7;
    int u = idx & 127;
    int ch = u >> 2, pos = u & 3;
    int tok = g_tokOfSlot[slot];
    int row = x[tok];
    pack_unit(embed + (size_t)row * DMODEL + ch * 32 + pos * 8,
              g_hpk + (size_t)((slot >> 7) * 32 + ch) * ABLK_H + (slot & 127) * 40 + pos * 8);
}

// ---------------- combine + LN -> packed head A ------------------------------
__global__ void combine_ln_kernel(const float* __restrict__ gamma,
                                  const float* __restrict__ beta) {
    int t = blockIdx.x, tid = threadIdx.x;
    int s0 = g_slot[2 * t], s1 = g_slot[2 * t + 1];
    float w0 = g_w[2 * t], w1 = g_w[2 * t + 1];

    float4 a = ((const float4*)(g_y + (size_t)s0 * DMODEL))[tid];
    float4 b = ((const float4*)(g_y + (size_t)s1 * DMODEL))[tid];
    float4 c;
    c.x = w0 * a.x + w1 * b.x;  c.y = w0 * a.y + w1 * b.y;
    c.z = w0 * a.z + w1 * b.z;  c.w = w0 * a.w + w1 * b.w;

    float sum = c.x + c.y + c.z + c.w;
    float ssq = c.x*c.x + c.y*c.y + c.z*c.z + c.w*c.w;
    for (int o = 16; o > 0; o >>= 1) {
        sum += __shfl_xor_sync(0xffffffffu, sum, o);
        ssq += __shfl_xor_sync(0xffffffffu, ssq, o);
    }
    __shared__ float rs[8], rq[8];
    __shared__ float s_mu, s_rstd;
    int warp = tid >> 5, lane = tid & 31;
    if (lane == 0) { rs[warp] = sum; rq[warp] = ssq; }
    __syncthreads();
    if (tid == 0) {
        float S = 0.f, Q = 0.f;
#pragma unroll
        for (int w = 0; w < 8; w++) { S += rs[w]; Q += rq[w]; }
        float mu = S / (float)DMODEL;
        float var = Q / (float)DMODEL - mu * mu;
        s_mu = mu;
        s_rstd = rsqrtf(var + LN_EPS);
    }
    __syncthreads();
    float mu = s_mu, rstd = s_rstd;
    float4 g4 = ((const float4*)gamma)[tid];
    float4 b4 = ((const float4*)beta)[tid];
    uint2 o;
    o.x = h2u(__floats2half2_rn((c.x - mu) * rstd * g4.x + b4.x,
                                (c.y - mu) * rstd * g4.y + b4.y));
    o.y = h2u(__floats2half2_rn((c.z - mu) * rstd * g4.z + b4.z,
                                (c.w - mu) * rstd * g4.w + b4.w));
    int d0 = tid * 4;
    int ch = d0 >> 5, c2 = d0 & 31;
    __half* dst = g_xpk + (size_t)((t >> 7) * 32 + ch) * ABLK_H + (t & 127) * 40 + c2;
    *(uint2*)dst = o;
}

// ============ per-stage body: warp-rotated k-step order ======================
// Warp w processes ksteps in order (kRot, kRot+1, kRot+2, kRot+3) mod 4, so
// the 4 warps per SMSP stagger their ldsm bursts against each other's MMAs.
// All 4 ksteps are resident once full[s] fires, so any order is valid
// (fp32 accumulation reorder only). Release after this warp's last ldsm.
#define DO_STAGE(sIdx)                                                         \
    do {                                                                       \
        uint32_t sbase = smb + (uint32_t)(sIdx) * STG2;                        \
        _Pragma("unroll")                                                      \
        for (int kk = 0; kk < 4; kk++) {                                       \
            int ke = (kk + kRot) & 3;                                          \
            int sub = ke >> 1, ksl = ke & 1;                                   \
            uint32_t ab = sbase + (uint32_t)sub * ABLK_B;                      \
            uint32_t bb = sbase + 2 * ABLK_B + (uint32_t)sub * BBLK_B;         \
            _Pragma("unroll")                                                  \
            for (int mb = 0; mb < 4; mb++)                                     \
                ldsm4(af[mb], ab + (uint32_t)((wmOff + mb * 16 + aRow) * 5 + ksl * 2 + aKu) * 16); \
            _Pragma("unroll")                                                  \
            for (int p = 0; p < 2; p++) {                                      \
                uint32_t rr[4];                                                \
                ldsm4t(rr, bb + (uint32_t)((ksl * 16 + bK) * 33 + bNu + p * 2) * 16); \
                bf[2 * p][0] = rr[0]; bf[2 * p][1] = rr[1];                    \
                bf[2 * p + 1][0] = rr[2]; bf[2 * p + 1][1] = rr[3];            \
            }                                                                  \
            if (kk == 3) {                                                     \
                __syncwarp();                                                  \
                if (lane == 0) MBAR_ARRIVE(mbE + (sIdx) * 8);                  \
            }                                                                  \
            _Pragma("unroll")                                                  \
            for (int mb = 0; mb < 4; mb++)                                     \
                _Pragma("unroll")                                              \
                for (int nb = 0; nb < 4; nb++)                                 \
                    mma_f16(acc[mb][nb], af[mb], bf[nb]);                      \
        }                                                                      \
    } while (0)

// ---------------- persistent grouped fp16 GEMM (FFN1/FFN2) -------------------
template <int K, int N, bool RELU, int OUT>
__global__ void __launch_bounds__(512, 1)
fgemm_persist(const __half* __restrict__ Apk, const __half* __restrict__ Bpk,
              const float* __restrict__ biasAll, void* __restrict__ Cout) {
    extern __shared__ __align__(128) char smc[];
    const int NCH = K / KCH;
    const int NC2 = K / (2 * KCH);
    const int NSTRIPE = N / NT;

    int bid = blockIdx.x;
    int nCTA = gridDim.x;
    int mtot = g_mtot;
    int ntiles = mtot * NSTRIPE;
    int nMy = (bid < ntiles) ? ((ntiles - 1 - bid) / nCTA + 1) : 0;
    if (nMy == 0) return;
    int totalStages = nMy * NC2;

    int tid = threadIdx.x;
    int wid = tid >> 5, lane = tid & 31;
    int wm = wid >> 3, wn = wid & 7;
    int wmOff = wm * 64, wnOff = wn * 32;
    int g = lane >> 2, tg = lane & 3;
    int b3 = lane >> 3, r8 = lane & 7;
    int aRow = (b3 & 1) * 8 + r8;
    int aKu  = b3 >> 1;
    int bK   = (b3 & 1) * 8 + r8;
    int bNu  = (b3 >> 1) + (wnOff >> 3);
    int kRot = wid & 3;

    uint32_t smb = smem_u32(smc);
    uint32_t mbF = smb + MBOFF;
    uint32_t mbE = smb + MBOFF + 64;

    if (tid == 0) {
#pragma unroll
        for (int s = 0; s < NSTG; s++) {
            MBAR_INIT(mbF + s * 8, 1);
            MBAR_INIT(mbE + s * 8, 16);
        }
    }
    __syncthreads();

    auto decomp = [&](int tile, int& e, int& mt, int& n) {
        mt = tile % mtot;
        n = tile / mtot;
        e = 0;
#pragma unroll
        for (int q = 1; q < NEXP; q++)
            if (g_mOff[q] <= mt) e = q;
    };

    auto issue = [&](int gc) {
        int s = gc & (NSTG - 1);
        int tileSeq = gc / NC2;
        int c2 = gc - tileSeq * NC2;
        int tile = bid + tileSeq * nCTA;
        int e, mt, n;
        decomp(tile, e, mt, n);
        const __half* Ab = Apk + ((size_t)mt * NCH + 2 * c2) * ABLK_H;
        const __half* Bb = Bpk + ((size_t)(e * NSTRIPE + n) * NCH + 2 * c2) * BBLK_H;
        uint32_t stg = smb + (uint32_t)s * STG2;
        uint32_t mb = mbF + s * 8;
        MBAR_EXPECT_TX(mb, STG2);
        bulk_ld(stg, Ab, 2 * ABLK_B, mb);
        bulk_ld(stg + 2 * ABLK_B, Bb, 2 * BBLK_B, mb);
    };

    if (tid == 0) {
        int pre = totalStages < NSTG ? totalStages : NSTG;
        for (int c0 = 0; c0 < pre; c0++) issue(c0);
    }

    uint32_t af[4][4];
    uint32_t bf[4][2];
    int gc = 0;

    for (int tseq = 0; tseq < nMy; tseq++) {
        int tile = bid + tseq * nCTA;
        int e, mt, n;
        decomp(tile, e, mt, n);
        int cnt = g_cnt[e];
        int rowLoc = (mt - g_mOff[e]) * MT;

        float acc[4][4][4];
#pragma unroll
        for (int i = 0; i < 4; i++)
#pragma unroll
            for (int j = 0; j < 4; j++)
#pragma unroll
                for (int q = 0; q < 4; q++) acc[i][j][q] = 0.f;

        for (int c2 = 0; c2 < NC2; c2++, gc++) {
            int s = gc & (NSTG - 1);
            int par = (gc >> 2) & 1;
            MBAR_WAIT(mbF + s * 8, par);
            DO_STAGE(s);
            if (tid == 0 && gc + NSTG < totalStages) {
                MBAR_WAIT(mbE + s * 8, par);
                issue(gc + NSTG);
            }
        }

        const float* bias = biasAll + (size_t)e * N;
        int colBlock = n * NT;
#pragma unroll
        for (int nb = 0; nb < 4; nb++) {
            int col = colBlock + wnOff + nb * 8 + tg * 2;
            float2 bv = *(const float2*)(bias + col);
#pragma unroll
            for (int mb = 0; mb < 4; mb++) {
                int mr = wmOff + mb * 16 + g;
#pragma unroll
                for (int h = 0; h < 2; h++) {
                    int rr2 = mr + h * 8;
                    if (rowLoc + rr2 < cnt) {
                        float ox = acc[mb][nb][2 * h]     + bv.x;
                        float oy = acc[mb][nb][2 * h + 1] + bv.y;
                        if (RELU) { ox = fmaxf(ox, 0.f); oy = fmaxf(oy, 0.f); }
                        int R = mt * MT + rr2;
                        if (OUT == 1) {
                            __half* dst = (__half*)Cout +
                                (size_t)((R >> 7) * (N / 32) + (col >> 5)) * ABLK_H +
                                (R & 127) * 40 + (col & 31);
                            *(__half2*)dst = __floats2half2_rn(ox, oy);
                        } else {
                            *(float2*)((float*)Cout + (size_t)R * N + col) =
                                make_float2(ox, oy);
                        }
                    }
                }
            }
        }
    }
}

// ---------------- persistent head GEMM ---------------------------------------
#define H_NCH   (DMODEL / KCH)
#define H_NC2   (DMODEL / (2 * KCH))
#define H_TM    16
#define H_TN    125
#define H_NTILES (H_TM * H_TN)

__global__ void __launch_bounds__(512, 1)
hgemm_persist(const __half* __restrict__ Apk, const __half* __restrict__ Bpk,
              const float* __restrict__ bias, float* __restrict__ out) {
    extern __shared__ __align__(128) char smc[];
    int bid = blockIdx.x;
    int nCTA = gridDim.x;

    int nMy = (bid < H_NTILES) ? ((H_NTILES - 1 - bid) / nCTA + 1) : 0;
    if (nMy == 0) return;
    int totalStages = nMy * H_NC2;

    int tid = threadIdx.x;
    int wid = tid >> 5, lane = tid & 31;
    int wm = wid >> 3, wn = wid & 7;
    int wmOff = wm * 64, wnOff = wn * 32;
    int g = lane >> 2, tg = lane & 3;
    int b3 = lane >> 3, r8 = lane & 7;
    int aRow = (b3 & 1) * 8 + r8;
    int aKu  = b3 >> 1;
    int bK   = (b3 & 1) * 8 + r8;
    int bNu  = (b3 >> 1) + (wnOff >> 3);
    int kRot = wid & 3;

    uint32_t smb = smem_u32(smc);
    uint32_t mbF = smb + MBOFF;
    uint32_t mbE = smb + MBOFF + 64;

    if (tid == 0) {
#pragma unroll
        for (int s = 0; s < NSTG; s++) {
            MBAR_INIT(mbF + s * 8, 1);
            MBAR_INIT(mbE + s * 8, 16);
        }
    }
    __syncthreads();

    auto issue = [&](int gc) {
        int s = gc & (NSTG - 1);
        int tileSeq = gc / H_NC2;
        int c2 = gc - tileSeq * H_NC2;
        int tile = bid + tileSeq * nCTA;
        int m = tile & (H_TM - 1);
        int n = tile >> 4;
        const __half* Ab = Apk + ((size_t)m * H_NCH + 2 * c2) * ABLK_H;
        const __half* Bb = Bpk + ((size_t)n * H_NCH + 2 * c2) * BBLK_H;
        uint32_t stg = smb + (uint32_t)s * STG2;
        uint32_t mb = mbF + s * 8;
        MBAR_EXPECT_TX(mb, STG2);
        bulk_ld(stg, Ab, 2 * ABLK_B, mb);
        bulk_ld(stg + 2 * ABLK_B, Bb, 2 * BBLK_B, mb);
    };

    if (tid == 0) {
        int pre = totalStages < NSTG ? totalStages : NSTG;
        for (int c0 = 0; c0 < pre; c0++) issue(c0);
    }

    uint32_t af[4][4];
    uint32_t bf[4][2];
    int gc = 0;

    for (int tile = bid; tile < H_NTILES; tile += nCTA) {
        int m = tile & (H_TM - 1);
        int n = tile >> 4;

        float acc[4][4][4];
#pragma unroll
        for (int i = 0; i < 4; i++)
#pragma unroll
            for (int j = 0; j < 4; j++)
#pragma unroll
                for (int q = 0; q < 4; q++) acc[i][j][q] = 0.f;

        for (int c2 = 0; c2 < H_NC2; c2++, gc++) {
            int s = gc & (NSTG - 1);
            int par = (gc >> 2) & 1;
            MBAR_WAIT(mbF + s * 8, par);
            DO_STAGE(s);
            if (tid == 0 && gc + NSTG < totalStages) {
                MBAR_WAIT(mbE + s * 8, par);
                issue(gc + NSTG);
            }
        }

        int rowBase = m * MT;
        int colBase = n * NT;
#pragma unroll
        for (int nb = 0; nb < 4; nb++) {
            int col = colBase + wnOff + nb * 8 + tg * 2;
            float2 bv = *(const float2*)(bias + col);
#pragma unroll
            for (int mb = 0; mb < 4; mb++) {
                int mr = rowBase + wmOff + mb * 16 + g;
#pragma unroll
                for (int h = 0; h < 2; h++) {
                    float ox = acc[mb][nb][2 * h]     + bv.x;
                    float oy = acc[mb][nb][2 * h + 1] + bv.y;
                    *(float2*)(out + (size_t)(mr + h * 8) * VOCABSZ + col) =
                        make_float2(ox, oy);
                }
            }
        }
    }
}

// ---------------- launch ----------------------------------------------------
extern "C" void kernel_launch(void* const* d_in, const int* in_sizes, int n_in,
                              void* d_out, int out_size) {
    const int*   x     = (const int*)  d_in[0];
    const float* embed = (const float*)d_in[1];
    const float* Wg    = (const float*)d_in[2];
    const float* bg    = (const float*)d_in[3];
    const float* W1    = (const float*)d_in[4];
    const float* b1    = (const float*)d_in[5];
    const float* W2    = (const float*)d_in[6];
    const float* b2    = (const float*)d_in[7];
    const float* gamma = (const float*)d_in[8];
    const float* beta  = (const float*)d_in[9];
    const float* Wh    = (const float*)d_in[10];
    const float* bh    = (const float*)d_in[11];
    float* out = (float*)d_out;

    __half *p_hpk, *p_apk, *p_xpk, *p_Whp, *p_W1p, *p_W2p;
    float *p_y;
    cudaGetSymbolAddress((void**)&p_hpk, g_hpk);
    cudaGetSymbolAddress((void**)&p_apk, g_apk);
    cudaGetSymbolAddress((void**)&p_xpk, g_xpk);
    cudaGetSymbolAddress((void**)&p_Whp, g_Whp);
    cudaGetSymbolAddress((void**)&p_W1p, g_W1p);
    cudaGetSymbolAddress((void**)&p_W2p, g_W2p);
    cudaGetSymbolAddress((void**)&p_y,   g_y);

    cudaFuncSetAttribute((const void*)fgemm_persist<DMODEL, HIDDEN, true, 1>,
                         cudaFuncAttributeMaxDynamicSharedMemorySize, SMEM_SZ);
    cudaFuncSetAttribute((const void*)fgemm_persist<HIDDEN, DMODEL, false, 0>,
                         cudaFuncAttributeMaxDynamicSharedMemorySize, SMEM_SZ);
    cudaFuncSetAttribute((const void*)hgemm_persist,
                         cudaFuncAttributeMaxDynamicSharedMemorySize, SMEM_SZ);

    static cudaStream_t s1 = nullptr;
    static cudaEvent_t evFork = nullptr, evJoin = nullptr;
    if (s1 == nullptr) {
        cudaStreamCreateWithFlags(&s1, cudaStreamNonBlocking);
        cudaEventCreateWithFlags(&evFork, cudaEventDisableTiming);
        cudaEventCreateWithFlags(&evJoin, cudaEventDisableTiming);
    }

    cudaEventRecord(evFork, 0);
    cudaStreamWaitEvent(s1, evFork, 0);
    prep2_kernel<<<P2BLOCKS, 256, 0, s1>>>(W2, Wh);
    cudaEventRecord(evJoin, s1);

    prep1_kernel<<<W1BLOCKS + TOKENS, 256>>>(x, embed, Wg, bg, W1);
    scan_assign_kernel<<<1, 1024>>>();
    pack_h_kernel<<<(NSLOTPAD * 128 + 255) / 256, 256>>>(x, embed);

    fgemm_persist<DMODEL, HIDDEN, true, 1>
        <<<NSM, 512, SMEM_SZ>>>(p_hpk, p_W1p, b1, p_apk);

    cudaStreamWaitEvent(0, evJoin, 0);

    fgemm_persist<HIDDEN, DMODEL, false, 0>
        <<<NSM, 512, SMEM_SZ>>>(p_apk, p_W2p, b2, p_y);

    combine_ln_kernel<<<TOKENS, 256>>>(gamma, beta);

    hgemm_persist<<<NSM, 512, SMEM_SZ>>>(p_xpk, p_Whp, bh, out);
}

// round 17
// speedup vs baseline: 1.0546x; 1.0546x over previous
#include <cuda_runtime.h>
#include <cuda_fp16.h>
#include <cstdint>
#include <math.h>

#define TOKENS   2048
#define DMODEL   1024
#define HIDDEN   2048
#define NEXP     8
#define VOCABSZ  32000
#define LN_EPS   1e-5f

#define MT 128
#define NT 256
#define KCH 32
#define NSTG 4
#define ABLK_B   10240
#define BBLK_B   16896
#define ABLK_H   5120
#define BBLK_H   8448
#define STG2 (2 * (ABLK_B + BBLK_B))
#define MBOFF (NSTG * STG2)
#define SMEM_SZ (MBOFF + 128)

#define NSLOTPAD 5120
#define SLOTTILES 40
#define NSM 152

// ---------------- scratch ----------------------------------------------------
__device__ float g_w  [TOKENS * 2];
__device__ int   g_eidx[TOKENS * 2];
__device__ int   g_slot[TOKENS * 2];
__device__ int   g_tokOfSlot[NSLOTPAD];
__device__ int   g_cnt[NEXP];
__device__ int   g_off[NEXP + 1];
__device__ int   g_mOff[NEXP];
__device__ int   g_mtot;
__device__ float g_y  [NSLOTPAD * DMODEL];
__device__ __align__(16) __half g_hpk [SLOTTILES * 32 * ABLK_H];
__device__ __align__(16) __half g_apk [SLOTTILES * 64 * ABLK_H];
__device__ __align__(16) __half g_xpk [16 * 32 * ABLK_H];
__device__ __align__(16) __half g_Whp [125 * 32 * BBLK_H];
__device__ __align__(16) __half g_W1p [NEXP * 8 * 32 * BBLK_H];
__device__ __align__(16) __half g_W2p [NEXP * 4 * 64 * BBLK_H];

// ---------------- helpers ----------------------------------------------------
__device__ __forceinline__ uint32_t h2u(__half2 h) {
    return *reinterpret_cast<uint32_t*>(&h);
}
__device__ __forceinline__ uint32_t smem_u32(const void* p) {
    uint32_t a;
    asm("{ .reg .u64 t; cvta.to.shared.u64 t, %1; cvt.u32.u64 %0, t; }"
        : "=r"(a) : "l"(p));
    return a;
}
__device__ __forceinline__ void mma_f16(float c[4], const uint32_t a[4],
                                        const uint32_t b[2]) {
    asm volatile(
        "mma.sync.aligned.m16n8k16.row.col.f32.f16.f16.f32 "
        "{%0,%1,%2,%3}, {%4,%5,%6,%7}, {%8,%9}, {%0,%1,%2,%3};"
        : "+f"(c[0]), "+f"(c[1]), "+f"(c[2]), "+f"(c[3])
        : "r"(a[0]), "r"(a[1]), "r"(a[2]), "r"(a[3]), "r"(b[0]), "r"(b[1]));
}
__device__ __forceinline__ void ldsm4(uint32_t r[4], uint32_t addr) {
    asm volatile("ldmatrix.sync.aligned.m8n8.x4.shared.b16 {%0,%1,%2,%3}, [%4];"
                 : "=r"(r[0]), "=r"(r[1]), "=r"(r[2]), "=r"(r[3]) : "r"(addr));
}
__device__ __forceinline__ void ldsm4t(uint32_t r[4], uint32_t addr) {
    asm volatile("ldmatrix.sync.aligned.m8n8.x4.trans.shared.b16 {%0,%1,%2,%3}, [%4];"
                 : "=r"(r[0]), "=r"(r[1]), "=r"(r[2]), "=r"(r[3]) : "r"(addr));
}
#define MBAR_INIT(a, n) \
    asm volatile("mbarrier.init.shared.b64 [%0], %1;" :: "r"((uint32_t)(a)), "r"((uint32_t)(n)) : "memory")
#define MBAR_EXPECT_TX(a, b) \
    asm volatile("mbarrier.arrive.expect_tx.shared.b64 _, [%0], %1;" :: "r"((uint32_t)(a)), "r"((uint32_t)(b)) : "memory")
#define MBAR_ARRIVE(a) \
    asm volatile("mbarrier.arrive.shared.b64 _, [%0];" :: "r"((uint32_t)(a)) : "memory")
#define MBAR_WAIT(a, par) do { \
    uint32_t _mb = (uint32_t)(a); uint32_t _pa = (uint32_t)(par); uint32_t _dn; \
    asm volatile("{\n\t.reg .pred p;\n\t" \
        "mbarrier.try_wait.parity.acquire.cta.shared::cta.b64 p, [%1], %2;\n\t" \
        "selp.b32 %0, 1, 0, p;\n\t}" : "=r"(_dn) : "r"(_mb), "r"(_pa) : "memory"); \
    if (!_dn) { \
        asm volatile("{\n\t.reg .pred P1;\n\t" \
            "WL_%=:\n\t" \
            "mbarrier.try_wait.parity.acquire.cta.shared::cta.b64 P1, [%0], %1, 0x989680;\n\t" \
            "@P1 bra.uni WD_%=;\n\t" \
            "bra.uni WL_%=;\n\t" \
            "WD_%=:\n\t}" :: "r"(_mb), "r"(_pa) : "memory"); \
    } } while (0)
__device__ __forceinline__ void bulk_ld(uint32_t dst, const void* src,
                                        uint32_t bytes, uint32_t mbar) {
    asm volatile(
        "cp.async.bulk.shared::cluster.global.mbarrier::complete_tx::bytes "
        "[%0], [%1], %2, [%3];"
        :: "r"(dst), "l"(src), "r"(bytes), "r"(mbar) : "memory");
}

// ---------------- pack unit helper -------------------------------------------
__device__ __forceinline__ void pack_unit(const float* src, __half* dst) {
    float4 v0 = *(const float4*)src;
    float4 v1 = *(const float4*)(src + 4);
    uint4 o;
    o.x = h2u(__floats2half2_rn(v0.x, v0.y));
    o.y = h2u(__floats2half2_rn(v0.z, v0.w));
    o.z = h2u(__floats2half2_rn(v1.x, v1.y));
    o.w = h2u(__floats2half2_rn(v1.z, v1.w));
    *(uint4*)dst = o;
}

#define WH_UNITS (125 * 32 * 32 * 32)
#define W1_UNITS (NEXP * 8 * 32 * 32 * 32)
#define W2_UNITS (NEXP * 4 * 64 * 32 * 32)
#define W1BLOCKS ((W1_UNITS + 255) / 256)
#define P2BLOCKS ((W2_UNITS + WH_UNITS + 255) / 256)

// ---------------- stream0: pack W1 + gate ------------------------------------
__global__ void prep1_kernel(const int* __restrict__ x,
                             const float* __restrict__ embed,
                             const float* __restrict__ Wg,
                             const float* __restrict__ bg,
                             const float* __restrict__ W1) {
    if (blockIdx.x < W1BLOCKS) {
        int i = blockIdx.x * blockDim.x + threadIdx.x;
        if (i >= W1_UNITS) return;
        int u = i & 31, k = (i >> 5) & 31, ch = (i >> 10) & 31, st = (i >> 15) & 7, e = i >> 18;
        pack_unit(W1 + (size_t)e * DMODEL * HIDDEN + (size_t)(ch * 32 + k) * HIDDEN + st * 256 + u * 8,
                  g_W1p + (size_t)((e * 8 + st) * 32 + ch) * BBLK_H + k * 264 + u * 8);
        return;
    }
    int t   = blockIdx.x - W1BLOCKS;
    int tid = threadIdx.x;
    int row = x[t];
    float4 v = ((const float4*)(embed + (size_t)row * DMODEL))[tid];

    float p[NEXP];
#pragma unroll
    for (int e = 0; e < NEXP; e++) p[e] = 0.f;
    float hv[4] = {v.x, v.y, v.z, v.w};
    int d0 = tid * 4;
#pragma unroll
    for (int j = 0; j < 4; j++) {
        const float* wgr = Wg + (size_t)(d0 + j) * NEXP;
#pragma unroll
        for (int e = 0; e < NEXP; e++) p[e] += hv[j] * wgr[e];
    }
#pragma unroll
    for (int e = 0; e < NEXP; e++)
        for (int o = 16; o > 0; o >>= 1)
            p[e] += __shfl_xor_sync(0xffffffffu, p[e], o);

    __shared__ float red[8][NEXP];
    int warp = tid >> 5, lane = tid & 31;
    if (lane == 0)
#pragma unroll
        for (int e = 0; e < NEXP; e++) red[warp][e] = p[e];
    __syncthreads();

    if (tid == 0) {
        float g[NEXP];
#pragma unroll
        for (int e = 0; e < NEXP; e++) {
            g[e] = bg[e];
#pragma unroll
            for (int w = 0; w < 8; w++) g[e] += red[w][e];
        }
        float mx = g[0];
#pragma unroll
        for (int e = 1; e < NEXP; e++) mx = fmaxf(mx, g[e]);
        float s = 0.f, pr[NEXP];
#pragma unroll
        for (int e = 0; e < NEXP; e++) { pr[e] = expf(g[e] - mx); s += pr[e]; }
        float inv = 1.f / s;
#pragma unroll
        for (int e = 0; e < NEXP; e++) pr[e] *= inv;

        int i0 = 0;
#pragma unroll
        for (int e = 1; e < NEXP; e++) if (pr[e] > pr[i0]) i0 = e;
        int i1 = (i0 == 0) ? 1 : 0;
#pragma unroll
        for (int e = 0; e < NEXP; e++)
            if (e != i0 && pr[e] > pr[i1]) i1 = e;

        g_w[2 * t]     = pr[i0];  g_eidx[2 * t]     = i0;
        g_w[2 * t + 1] = pr[i1];  g_eidx[2 * t + 1] = i1;
    }
}

// ---------------- stream1: pack W2 + Wh --------------------------------------
__global__ void prep2_kernel(const float* __restrict__ W2,
                             const float* __restrict__ Wh) {
    int idx = blockIdx.x * blockDim.x + threadIdx.x;
    if (idx < W2_UNITS) {
        int u = idx & 31, k = (idx >> 5) & 31, ch = (idx >> 10) & 63, st = (idx >> 16) & 3, e = idx >> 18;
        pack_unit(W2 + (size_t)e * HIDDEN * DMODEL + (size_t)(ch * 32 + k) * DMODEL + st * 256 + u * 8,
                  g_W2p + (size_t)((e * 4 + st) * 64 + ch) * BBLK_H + k * 264 + u * 8);
    } else if (idx < W2_UNITS + WH_UNITS) {
        int i = idx - W2_UNITS;
        int u = i & 31, k = (i >> 5) & 31, ch = (i >> 10) & 31, st = i >> 15;
        pack_unit(Wh + (size_t)(ch * 32 + k) * VOCABSZ + st * 256 + u * 8,
                  g_Whp + (size_t)(st * 32 + ch) * BBLK_H + k * 264 + u * 8);
    }
}

// ---------------- count + scan + slot assignment -----------------------------
__global__ void scan_assign_kernel() {
    __shared__ int s_cnt[NEXP];
    __shared__ int s_off[NEXP + 1];
    __shared__ int s_cur[NEXP];
    int tid = threadIdx.x;
    for (int i = tid; i < NSLOTPAD; i += blockDim.x) g_tokOfSlot[i] = 0;
    if (tid < NEXP) { s_cnt[tid] = 0; s_cur[tid] = 0; }
    __syncthreads();
    for (int i = tid; i < TOKENS * 2; i += blockDim.x)
        atomicAdd(&s_cnt[g_eidx[i]], 1);
    __syncthreads();
    if (tid == 0) {
        s_off[0] = 0;
        for (int e = 0; e < NEXP; e++) {
            s_off[e + 1] = s_off[e] + ((s_cnt[e] + 127) & ~127);
            g_cnt[e] = s_cnt[e];
        }
        for (int e = 0; e <= NEXP; e++) g_off[e] = s_off[e];
        for (int e = 0; e < NEXP; e++) g_mOff[e] = s_off[e] >> 7;
        g_mtot = s_off[NEXP] >> 7;
    }
    __syncthreads();
    for (int t = tid; t < TOKENS; t += blockDim.x) {
#pragma unroll
        for (int k = 0; k < 2; k++) {
            int e = g_eidx[2 * t + k];
            int pos = atomicAdd(&s_cur[e], 1);
            int slot = s_off[e] + pos;
            g_slot[2 * t + k] = slot;
            g_tokOfSlot[slot] = t;
        }
    }
}

// ---------------- pack FFN1 A ------------------------------------------------
__global__ void pack_h_kernel(const int* __restrict__ x,
                              const float* __restrict__ embed) {
    int idx = blockIdx.x * blockDim.x + threadIdx.x;
    if (idx >= NSLOTPAD * 128) return;
    int slot = idx >> 7;
    int u = idx & 127;
    int ch = u >> 2, pos = u & 3;
    int tok = g_tokOfSlot[slot];
    int row = x[tok];
    pack_unit(embed + (size_t)row * DMODEL + ch * 32 + pos * 8,
              g_hpk + (size_t)((slot >> 7) * 32 + ch) * ABLK_H + (slot & 127) * 40 + pos * 8);
}

// ---------------- combine + LN -> packed head A ------------------------------
__global__ void combine_ln_kernel(const float* __restrict__ gamma,
                                  const float* __restrict__ beta) {
    int t = blockIdx.x, tid = threadIdx.x;
    int s0 = g_slot[2 * t], s1 = g_slot[2 * t + 1];
    float w0 = g_w[2 * t], w1 = g_w[2 * t + 1];

    float4 a = ((const float4*)(g_y + (size_t)s0 * DMODEL))[tid];
    float4 b = ((const float4*)(g_y + (size_t)s1 * DMODEL))[tid];
    float4 c;
    c.x = w0 * a.x + w1 * b.x;  c.y = w0 * a.y + w1 * b.y;
    c.z = w0 * a.z + w1 * b.z;  c.w = w0 * a.w + w1 * b.w;

    float sum = c.x + c.y + c.z + c.w;
    float ssq = c.x*c.x + c.y*c.y + c.z*c.z + c.w*c.w;
    for (int o = 16; o > 0; o >>= 1) {
        sum += __shfl_xor_sync(0xffffffffu, sum, o);
        ssq += __shfl_xor_sync(0xffffffffu, ssq, o);
    }
    __shared__ float rs[8], rq[8];
    __shared__ float s_mu, s_rstd;
    int warp = tid >> 5, lane = tid & 31;
    if (lane == 0) { rs[warp] = sum; rq[warp] = ssq; }
    __syncthreads();
    if (tid == 0) {
        float S = 0.f, Q = 0.f;
#pragma unroll
        for (int w = 0; w < 8; w++) { S += rs[w]; Q += rq[w]; }
        float mu = S / (float)DMODEL;
        float var = Q / (float)DMODEL - mu * mu;
        s_mu = mu;
        s_rstd = rsqrtf(var + LN_EPS);
    }
    __syncthreads();
    float mu = s_mu, rstd = s_rstd;
    float4 g4 = ((const float4*)gamma)[tid];
    float4 b4 = ((const float4*)beta)[tid];
    uint2 o;
    o.x = h2u(__floats2half2_rn((c.x - mu) * rstd * g4.x + b4.x,
                                (c.y - mu) * rstd * g4.y + b4.y));
    o.y = h2u(__floats2half2_rn((c.z - mu) * rstd * g4.z + b4.z,
                                (c.w - mu) * rstd * g4.w + b4.w));
    int d0 = tid * 4;
    int ch = d0 >> 5, c2 = d0 & 31;
    __half* dst = g_xpk + (size_t)((t >> 7) * 32 + ch) * ABLK_H + (t & 127) * 40 + c2;
    *(uint2*)dst = o;
}

// ============ per-stage body: 8 warps, warp tile 64x64 =======================
// per kstep: 4 A-ldsm + 4 B-ldsm4t -> 32 HMMA. Release empty[s] after the
// last ldsm of the stage (sub1/ks1), before its MMA block.
#define DO_STAGE(sIdx)                                                         \
    do {                                                                       \
        uint32_t sbase = smb + (uint32_t)(sIdx) * STG2;                        \
        _Pragma("unroll")                                                      \
        for (int sub = 0; sub < 2; sub++) {                                    \
            uint32_t ab = sbase + (uint32_t)sub * ABLK_B;                      \
            uint32_t bb = sbase + 2 * ABLK_B + (uint32_t)sub * BBLK_B;         \
            _Pragma("unroll")                                                  \
            for (int ks = 0; ks < 2; ks++) {                                   \
                _Pragma("unroll")                                              \
                for (int mb = 0; mb < 4; mb++)                                 \
                    ldsm4(af[mb], ab + (uint32_t)((wmOff + mb * 16 + aRow) * 5 + ks * 2 + aKu) * 16); \
                _Pragma("unroll")                                              \
                for (int p = 0; p < 4; p++) {                                  \
                    uint32_t rr[4];                                            \
                    ldsm4t(rr, bb + (uint32_t)((ks * 16 + bK) * 33 + bNu + p * 2) * 16); \
                    bf[2 * p][0] = rr[0]; bf[2 * p][1] = rr[1];                \
                    bf[2 * p + 1][0] = rr[2]; bf[2 * p + 1][1] = rr[3];        \
                }                                                              \
                if (sub == 1 && ks == 1) {                                     \
                    __syncwarp();                                              \
                    if (lane == 0) MBAR_ARRIVE(mbE + (sIdx) * 8);              \
                }                                                              \
                _Pragma("unroll")                                              \
                for (int mb = 0; mb < 4; mb++)                                 \
                    _Pragma("unroll")                                          \
                    for (int nb = 0; nb < 8; nb++)                             \
                        mma_f16(acc[mb][nb], af[mb], bf[nb]);                  \
            }                                                                  \
        }                                                                      \
    } while (0)

#define GEMM_THREAD_SETUP                                                      \
    int tid = threadIdx.x;                                                     \
    int wid = tid >> 5, lane = tid & 31;                                       \
    int wm = wid >> 2, wn = wid & 3;                                           \
    int wmOff = wm * 64, wnOff = wn * 64;                                      \
    int g = lane >> 2, tg = lane & 3;                                          \
    int b3 = lane >> 3, r8 = lane & 7;                                         \
    int aRow = (b3 & 1) * 8 + r8;                                              \
    int aKu  = b3 >> 1;                                                        \
    int bK   = (b3 & 1) * 8 + r8;                                              \
    int bNu  = (b3 >> 1) + (wnOff >> 3);

// ---------------- persistent grouped fp16 GEMM (FFN1/FFN2) -------------------
template <int K, int N, bool RELU, int OUT>
__global__ void __launch_bounds__(256, 1)
fgemm_persist(const __half* __restrict__ Apk, const __half* __restrict__ Bpk,
              const float* __restrict__ biasAll, void* __restrict__ Cout) {
    extern __shared__ __align__(128) char smc[];
    const int NCH = K / KCH;
    const int NC2 = K / (2 * KCH);
    const int NSTRIPE = N / NT;

    int bid = blockIdx.x;
    int nCTA = gridDim.x;
    int mtot = g_mtot;
    int ntiles = mtot * NSTRIPE;
    int nMy = (bid < ntiles) ? ((ntiles - 1 - bid) / nCTA + 1) : 0;
    if (nMy == 0) return;
    int totalStages = nMy * NC2;

    GEMM_THREAD_SETUP

    uint32_t smb = smem_u32(smc);
    uint32_t mbF = smb + MBOFF;
    uint32_t mbE = smb + MBOFF + 64;

    if (tid == 0) {
#pragma unroll
        for (int s = 0; s < NSTG; s++) {
            MBAR_INIT(mbF + s * 8, 1);
            MBAR_INIT(mbE + s * 8, 8);
        }
    }
    __syncthreads();

    auto decomp = [&](int tile, int& e, int& mt, int& n) {
        mt = tile % mtot;
        n = tile / mtot;
        e = 0;
#pragma unroll
        for (int q = 1; q < NEXP; q++)
            if (g_mOff[q] <= mt) e = q;
    };

    auto issue = [&](int gc) {
        int s = gc & (NSTG - 1);
        int tileSeq = gc / NC2;
        int c2 = gc - tileSeq * NC2;
        int tile = bid + tileSeq * nCTA;
        int e, mt, n;
        decomp(tile, e, mt, n);
        const __half* Ab = Apk + ((size_t)mt * NCH + 2 * c2) * ABLK_H;
        const __half* Bb = Bpk + ((size_t)(e * NSTRIPE + n) * NCH + 2 * c2) * BBLK_H;
        uint32_t stg = smb + (uint32_t)s * STG2;
        uint32_t mb = mbF + s * 8;
        MBAR_EXPECT_TX(mb, STG2);
        bulk_ld(stg, Ab, 2 * ABLK_B, mb);
        bulk_ld(stg + 2 * ABLK_B, Bb, 2 * BBLK_B, mb);
    };

    if (tid == 0) {
        int pre = totalStages < NSTG ? totalStages : NSTG;
        for (int c0 = 0; c0 < pre; c0++) issue(c0);
    }

    uint32_t af[4][4];
    uint32_t bf[8][2];
    int gc = 0;

    for (int tseq = 0; tseq < nMy; tseq++) {
        int tile = bid + tseq * nCTA;
        int e, mt, n;
        decomp(tile, e, mt, n);
        int cnt = g_cnt[e];
        int rowLoc = (mt - g_mOff[e]) * MT;

        float acc[4][8][4];
#pragma unroll
        for (int i = 0; i < 4; i++)
#pragma unroll
            for (int j = 0; j < 8; j++)
#pragma unroll
                for (int q = 0; q < 4; q++) acc[i][j][q] = 0.f;

        for (int c2 = 0; c2 < NC2; c2++, gc++) {
            int s = gc & (NSTG - 1);
            int par = (gc >> 2) & 1;
            MBAR_WAIT(mbF + s * 8, par);
            DO_STAGE(s);
            if (tid == 0 && gc + NSTG < totalStages) {
                MBAR_WAIT(mbE + s * 8, par);
                issue(gc + NSTG);
            }
        }

        const float* bias = biasAll + (size_t)e * N;
        int colBlock = n * NT;
#pragma unroll
        for (int nb = 0; nb < 8; nb++) {
            int col = colBlock + wnOff + nb * 8 + tg * 2;
            float2 bv = *(const float2*)(bias + col);
#pragma unroll
            for (int mb = 0; mb < 4; mb++) {
                int mr = wmOff + mb * 16 + g;
#pragma unroll
                for (int h = 0; h < 2; h++) {
                    int rr2 = mr + h * 8;
                    if (rowLoc + rr2 < cnt) {
                        float ox = acc[mb][nb][2 * h]     + bv.x;
                        float oy = acc[mb][nb][2 * h + 1] + bv.y;
                        if (RELU) { ox = fmaxf(ox, 0.f); oy = fmaxf(oy, 0.f); }
                        int R = mt * MT + rr2;
                        if (OUT == 1) {
                            __half* dst = (__half*)Cout +
                                (size_t)((R >> 7) * (N / 32) + (col >> 5)) * ABLK_H +
                                (R & 127) * 40 + (col & 31);
                            *(__half2*)dst = __floats2half2_rn(ox, oy);
                        } else {
                            *(float2*)((float*)Cout + (size_t)R * N + col) =
                                make_float2(ox, oy);
                        }
                    }
                }
            }
        }
    }
}

// ---------------- persistent head GEMM ---------------------------------------
#define H_NCH   (DMODEL / KCH)
#define H_NC2   (DMODEL / (2 * KCH))
#define H_TM    16
#define H_TN    125
#define H_NTILES (H_TM * H_TN)

__global__ void __launch_bounds__(256, 1)
hgemm_persist(const __half* __restrict__ Apk, const __half* __restrict__ Bpk,
              const float* __restrict__ bias, float* __restrict__ out) {
    extern __shared__ __align__(128) char smc[];
    int bid = blockIdx.x;
    int nCTA = gridDim.x;

    int nMy = (bid < H_NTILES) ? ((H_NTILES - 1 - bid) / nCTA + 1) : 0;
    if (nMy == 0) return;
    int totalStages = nMy * H_NC2;

    GEMM_THREAD_SETUP

    uint32_t smb = smem_u32(smc);
    uint32_t mbF = smb + MBOFF;
    uint32_t mbE = smb + MBOFF + 64;

    if (tid == 0) {
#pragma unroll
        for (int s = 0; s < NSTG; s++) {
            MBAR_INIT(mbF + s * 8, 1);
            MBAR_INIT(mbE + s * 8, 8);
        }
    }
    __syncthreads();

    auto issue = [&](int gc) {
        int s = gc & (NSTG - 1);
        int tileSeq = gc / H_NC2;
        int c2 = gc - tileSeq * H_NC2;
        int tile = bid + tileSeq * nCTA;
        int m = tile & (H_TM - 1);
        int n = tile >> 4;
        const __half* Ab = Apk + ((size_t)m * H_NCH + 2 * c2) * ABLK_H;
        const __half* Bb = Bpk + ((size_t)n * H_NCH + 2 * c2) * BBLK_H;
        uint32_t stg = smb + (uint32_t)s * STG2;
        uint32_t mb = mbF + s * 8;
        MBAR_EXPECT_TX(mb, STG2);
        bulk_ld(stg, Ab, 2 * ABLK_B, mb);
        bulk_ld(stg + 2 * ABLK_B, Bb, 2 * BBLK_B, mb);
    };

    if (tid == 0) {
        int pre = totalStages < NSTG ? totalStages : NSTG;
        for (int c0 = 0; c0 < pre; c0++) issue(c0);
    }

    uint32_t af[4][4];
    uint32_t bf[8][2];
    int gc = 0;

    for (int tile = bid; tile < H_NTILES; tile += nCTA) {
        int m = tile & (H_TM - 1);
        int n = tile >> 4;

        float acc[4][8][4];
#pragma unroll
        for (int i = 0; i < 4; i++)
#pragma unroll
            for (int j = 0; j < 8; j++)
#pragma unroll
                for (int q = 0; q < 4; q++) acc[i][j][q] = 0.f;

        for (int c2 = 0; c2 < H_NC2; c2++, gc++) {
            int s = gc & (NSTG - 1);
            int par = (gc >> 2) & 1;
            MBAR_WAIT(mbF + s * 8, par);
            DO_STAGE(s);
            if (tid == 0 && gc + NSTG < totalStages) {
                MBAR_WAIT(mbE + s * 8, par);
                issue(gc + NSTG);
            }
        }

        int rowBase = m * MT;
        int colBase = n * NT;
#pragma unroll
        for (int nb = 0; nb < 8; nb++) {
            int col = colBase + wnOff + nb * 8 + tg * 2;
            float2 bv = *(const float2*)(bias + col);
#pragma unroll
            for (int mb = 0; mb < 4; mb++) {
                int mr = rowBase + wmOff + mb * 16 + g;
#pragma unroll
                for (int h = 0; h < 2; h++) {
                    float ox = acc[mb][nb][2 * h]     + bv.x;
                    float oy = acc[mb][nb][2 * h + 1] + bv.y;
                    *(float2*)(out + (size_t)(mr + h * 8) * VOCABSZ + col) =
                        make_float2(ox, oy);
                }
            }
        }
    }
}

// ---------------- launch ----------------------------------------------------
extern "C" void kernel_launch(void* const* d_in, const int* in_sizes, int n_in,
                              void* d_out, int out_size) {
    const int*   x     = (const int*)  d_in[0];
    const float* embed = (const float*)d_in[1];
    const float* Wg    = (const float*)d_in[2];
    const float* bg    = (const float*)d_in[3];
    const float* W1    = (const float*)d_in[4];
    const float* b1    = (const float*)d_in[5];
    const float* W2    = (const float*)d_in[6];
    const float* b2    = (const float*)d_in[7];
    const float* gamma = (const float*)d_in[8];
    const float* beta  = (const float*)d_in[9];
    const float* Wh    = (const float*)d_in[10];
    const float* bh    = (const float*)d_in[11];
    float* out = (float*)d_out;

    __half *p_hpk, *p_apk, *p_xpk, *p_Whp, *p_W1p, *p_W2p;
    float *p_y;
    cudaGetSymbolAddress((void**)&p_hpk, g_hpk);
    cudaGetSymbolAddress((void**)&p_apk, g_apk);
    cudaGetSymbolAddress((void**)&p_xpk, g_xpk);
    cudaGetSymbolAddress((void**)&p_Whp, g_Whp);
    cudaGetSymbolAddress((void**)&p_W1p, g_W1p);
    cudaGetSymbolAddress((void**)&p_W2p, g_W2p);
    cudaGetSymbolAddress((void**)&p_y,   g_y);

    cudaFuncSetAttribute((const void*)fgemm_persist<DMODEL, HIDDEN, true, 1>,
                         cudaFuncAttributeMaxDynamicSharedMemorySize, SMEM_SZ);
    cudaFuncSetAttribute((const void*)fgemm_persist<HIDDEN, DMODEL, false, 0>,
                         cudaFuncAttributeMaxDynamicSharedMemorySize, SMEM_SZ);
    cudaFuncSetAttribute((const void*)hgemm_persist,
                         cudaFuncAttributeMaxDynamicSharedMemorySize, SMEM_SZ);

    static cudaStream_t s1 = nullptr;
    static cudaEvent_t evFork = nullptr, evJoin = nullptr;
    if (s1 == nullptr) {
        cudaStreamCreateWithFlags(&s1, cudaStreamNonBlocking);
        cudaEventCreateWithFlags(&evFork, cudaEventDisableTiming);
        cudaEventCreateWithFlags(&evJoin, cudaEventDisableTiming);
    }

    cudaEventRecord(evFork, 0);
    cudaStreamWaitEvent(s1, evFork, 0);
    prep2_kernel<<<P2BLOCKS, 256, 0, s1>>>(W2, Wh);
    cudaEventRecord(evJoin, s1);

    prep1_kernel<<<W1BLOCKS + TOKENS, 256>>>(x, embed, Wg, bg, W1);
    scan_assign_kernel<<<1, 1024>>>();
    pack_h_kernel<<<(NSLOTPAD * 128 + 255) / 256, 256>>>(x, embed);

    fgemm_persist<DMODEL, HIDDEN, true, 1>
        <<<NSM, 256, SMEM_SZ>>>(p_hpk, p_W1p, b1, p_apk);

    cudaStreamWaitEvent(0, evJoin, 0);

    fgemm_persist<HIDDEN, DMODEL, false, 0>
        <<<NSM, 256, SMEM_SZ>>>(p_apk, p_W2p, b2, p_y);

    combine_ln_kernel<<<TOKENS, 256>>>(gamma, beta);

    hgemm_persist<<<NSM, 256, SMEM_SZ>>>(p_xpk, p_Whp, bh, out);
}